// round 17
// baseline (speedup 1.0000x reference)
#include <cuda_runtime.h>

#define NN      100000
#define EDIM    128
#define GRID    296                  // 2 blocks/SM on 148 SMs — co-residency guaranteed
#define TPB     512
#define WPB     (TPB / 32)           // 16 warps/block
#define NWARPS  (GRID * WPB)

// Persistent device scratch (no allocs in kernel_launch).
__device__ float    g_a[EDIM];
__device__ float    g_part[4 * 256];     // prep partials: [chunk][col]
__device__ float2   g_T1[NN];            // (s1, s1 + s3shift)
__device__ float2   g_T2[NN];            // (s2 + bias, s2 + s3shift + bias)
__device__ int      g_partmin[GRID];     // per-block qmin partials
__device__ unsigned g_bar;               // monotonic ticket barrier (replay-safe, never reset)

__device__ __forceinline__ void grid_barrier() {
    __syncthreads();
    if (threadIdx.x == 0) {
        __threadfence();
        unsigned ticket = atomicAdd(&g_bar, 1u);
        unsigned target = (ticket / GRID + 1u) * GRID;
        while (atomicAdd(&g_bar, 0u) < target) { }
        __threadfence();
    }
    __syncthreads();
}

__global__ void __launch_bounds__(TPB, 2)
fused_kernel(const float* __restrict__ z, const int* __restrict__ ei,
             const float* __restrict__ z0, const float* __restrict__ Wq,
             const float* __restrict__ Wo, const float* __restrict__ bo,
             float* __restrict__ out, int N, int E) {
    __shared__ float sa[EDIM], sb[EDIM], sc[EDIM];
    __shared__ float sw[32];
    __shared__ int   sred[WPB];
    __shared__ int   sqmin;
    __shared__ int4  s_si[2 * TPB];      // per-thread stash: 2 src int4 slots
    __shared__ int4  s_di[2 * TPB];      // per-thread stash: 2 dst int4 slots
    const int bid  = blockIdx.x;
    const int tid  = threadIdx.x;
    const int warp = tid >> 5;
    const int lane = tid & 31;

    // ───────── Phase 1a: prep partials (blocks 0..3, first 256 threads), coalesced
    if (bid < 4) {
        if (tid < 32) sw[tid] = Wo[EDIM + bid * 32 + tid];
        if (bid == 0 && tid >= 128 && tid < 256) g_a[tid - 128] = Wo[tid - 128];
        __syncthreads();
        if (tid < 256) {
            const float* base = Wq + (size_t)(bid * 32) * (2 * EDIM) + tid;
            float acc = 0.f;
            #pragma unroll
            for (int t = 0; t < 32; t++)
                acc += sw[t] * base[t * 2 * EDIM];
            g_part[bid * 256 + tid] = acc;
        }
    }

    const int E4     = E >> 2;
    const int stride = GRID * TPB;
    const int idx0   = bid * TPB + tid;

    // ───────── Phase 1b: qmin sweep + FREE index stash (same bytes, STS side-effect)
    {
        const int4* s4p = (const int4*)ei;
        const int4* d4p = (const int4*)(ei + E);
        int local = 0x7fffffff;
        int slot = 0;
        for (int i = idx0; i < E4; i += stride) {
            int4 s = s4p[i];
            int4 d = d4p[i];
            if (slot < 2) { s_si[slot * TPB + tid] = s; s_di[slot * TPB + tid] = d; }
            slot++;
            int m0 = max(s.x, d.x), m1 = max(s.y, d.y);
            int m2 = max(s.z, d.z), m3 = max(s.w, d.w);
            local = min(local, min(min(m0, m1), min(m2, m3)));
        }
        for (int e = (E4 << 2) + idx0; e < E; e += stride)
            local = min(local, max(ei[e], ei[E + e]));
        #pragma unroll
        for (int o = 16; o; o >>= 1)
            local = min(local, __shfl_xor_sync(0xffffffffu, local, o));
        if (lane == 0) sred[warp] = local;
        __syncthreads();
        if (tid == 0) {
            int v = sred[0];
            #pragma unroll
            for (int w = 1; w < WPB; w++) v = min(v, sred[w]);
            g_partmin[bid] = v;
        }
    }

    grid_barrier();

    // ───────── Phase 2 prologue: fold prep partials + reduce qmin partials
    if (tid < 256) {
        float v = g_part[tid] + g_part[256 + tid] + g_part[512 + tid] + g_part[768 + tid];
        if (tid < EDIM) { sa[tid] = g_a[tid]; sb[tid] = v; }
        else            { sc[tid - EDIM] = v; }
    }
    if (warp == WPB - 1) {
        int v = 0x7fffffff;
        #pragma unroll
        for (int t = 0; t < (GRID + 31) / 32; t++) {
            int idx = lane + 32 * t;
            if (idx < GRID) v = min(v, g_partmin[idx]);
        }
        #pragma unroll
        for (int o = 16; o; o >>= 1)
            v = min(v, __shfl_xor_sync(0xffffffffu, v, o));
        if (lane == 0) sqmin = v;
    }
    __syncthreads();

    // ───────── Phase 2: node tables, 4 nodes/warp per iteration, grid-stride (R11)
    {
        const int   qmin = sqmin;
        const float bias = bo[0];
        const int   k    = lane * 4;
        const int   wg   = bid * WPB + warp;

        for (int node0 = wg * 4; node0 < N; node0 += NWARPS * 4) {
            float4 vz[4], w4[4];
            bool   hasw[4];
            #pragma unroll
            for (int t = 0; t < 4; t++) {
                int node = node0 + t;
                int nc   = (node < N) ? node : (N - 1);
                vz[t] = ((const float4*)(z + (size_t)nc * EDIM))[lane];
                int m = nc - qmin;
                hasw[t] = (m >= 0);
                int mc = hasw[t] ? m : 0;
                w4[t] = ((const float4*)(z0 + (size_t)mc * EDIM))[lane];
            }
            #pragma unroll
            for (int t = 0; t < 4; t++) {
                int node = node0 + t;
                float s1 = vz[t].x * sa[k] + vz[t].y * sa[k+1] + vz[t].z * sa[k+2] + vz[t].w * sa[k+3];
                float s2 = vz[t].x * sb[k] + vz[t].y * sb[k+1] + vz[t].z * sb[k+2] + vz[t].w * sb[k+3];
                float s3 = hasw[t]
                         ? (w4[t].x * sc[k] + w4[t].y * sc[k+1] + w4[t].z * sc[k+2] + w4[t].w * sc[k+3])
                         : 0.f;
                #pragma unroll
                for (int o = 16; o; o >>= 1) {
                    s1 += __shfl_xor_sync(0xffffffffu, s1, o);
                    s2 += __shfl_xor_sync(0xffffffffu, s2, o);
                    s3 += __shfl_xor_sync(0xffffffffu, s3, o);
                }
                if (lane == 0 && node < N) {
                    g_T1[node] = make_float2(s1, s1 + s3);
                    g_T2[node] = make_float2(s2 + bias, s2 + s3 + bias);
                }
            }
        }
    }

    grid_barrier();

    // ───────── Phase 3: edges in phase-1b mapping; indices from smem stash.
    //           Slots 0..1 cover all of E4 at this grid (stride*2 >= E4);
    //           generic gmem fallbacks keep it shape-safe.
    {
        float4* out4 = (float4*)out;
        const int i0 = idx0;
        const int i1 = idx0 + stride;

        if (i0 < E4) {
            const bool h1 = (i1 < E4);
            int4 sA = s_si[tid],       dA = s_di[tid];
            int4 sB = make_int4(0,0,0,0), dB = sB;
            if (h1) { sB = s_si[TPB + tid]; dB = s_di[TPB + tid]; }

            int s[8] = { sA.x, sA.y, sA.z, sA.w, sB.x, sB.y, sB.z, sB.w };
            int d[8] = { dA.x, dA.y, dA.z, dA.w, dB.x, dB.y, dB.z, dB.w };
            const int nv = h1 ? 8 : 4;
            float2 u[8], v[8];
            #pragma unroll
            for (int t = 0; t < 8; t++) if (t < nv) u[t] = g_T1[s[t]];
            #pragma unroll
            for (int t = 0; t < 8; t++) if (t < nv) v[t] = g_T2[d[t]];
            float r[8];
            #pragma unroll
            for (int t = 0; t < 8; t++)
                if (t < nv) r[t] = (s[t] >= d[t]) ? (u[t].y + v[t].x) : (u[t].x + v[t].y);
            out4[i0] = make_float4(r[0], r[1], r[2], r[3]);
            if (h1) out4[i1] = make_float4(r[4], r[5], r[6], r[7]);
        }
        // any iterations beyond the 2 stashed slots (not hit at this problem size)
        const int4* s4p = (const int4*)ei;
        const int4* d4p = (const int4*)(ei + E);
        for (int i = idx0 + 2 * stride; i < E4; i += stride) {
            int4 s = s4p[i], d = d4p[i];
            float2 u0 = g_T1[s.x], u1 = g_T1[s.y], u2 = g_T1[s.z], u3 = g_T1[s.w];
            float2 v0 = g_T2[d.x], v1 = g_T2[d.y], v2 = g_T2[d.z], v3 = g_T2[d.w];
            float4 r;
            r.x = (s.x >= d.x) ? (u0.y + v0.x) : (u0.x + v0.y);
            r.y = (s.y >= d.y) ? (u1.y + v1.x) : (u1.x + v1.y);
            r.z = (s.z >= d.z) ? (u2.y + v2.x) : (u2.x + v2.y);
            r.w = (s.w >= d.w) ? (u3.y + v3.x) : (u3.x + v3.y);
            out4[i] = r;
        }
        // scalar tail (E not multiple of 4)
        for (int e = (E4 << 2) + idx0; e < E; e += stride) {
            int ss = ei[e], dd = ei[E + e];
            float2 u = g_T1[ss];
            float2 v = g_T2[dd];
            out[e] = (ss >= dd) ? (u.y + v.x) : (u.x + v.y);
        }
    }
}

extern "C" void kernel_launch(void* const* d_in, const int* in_sizes, int n_in,
                              void* d_out, int out_size) {
    // Inputs (metadata order): z, edge_index, z0, Wq, Wo, bo
    const float* z  = (const float*)d_in[0];
    const int*   ei = (const int*)d_in[1];      // jax default int32
    const float* z0 = (const float*)d_in[2];
    const float* Wq = (const float*)d_in[3];
    const float* Wo = (const float*)d_in[4];
    const float* bo = (const float*)d_in[5];
    float* out = (float*)d_out;

    int N = in_sizes[0] / EDIM;     // 100000
    int E = in_sizes[1] / 2;        // 1000000

    fused_kernel<<<GRID, TPB>>>(z, ei, z0, Wq, Wo, bo, out, N, E);
}